// round 15
// baseline (speedup 1.0000x reference)
#include <cuda_runtime.h>
#include <cuda_bf16.h>
#include <math.h>
#include <stdint.h>

#define Bq 2
#define Lq 2048
#define Sq 2048
#define Hq 8
#define Eq 64
#define TL 16
#define TS 128
#define NTHR 512
#define SCALE 0.125f

// smem layout (bytes): 3 stages; Q aliased into stage 2; sums after stages
#define STG_SZ   73728              // one stage: KHI|KLO|VHI|VLO, each 128*144
#define R_KHI    0
#define R_KLO    18432
#define R_VHI    36864
#define R_VLO    55296
#define OFF_QHI  147456             // stage-2 space (dead after prologue)
#define OFF_QLO  (OFF_QHI + 2304)
#define OFF_SUM  221184             // [16 rows][16 warps]
#define OFF_DOT  222208
#define OFF_INV  223232
#define SMEM_TOTAL 223296
#define OFF_RED  0                  // 64KB O-partials alias stage 0 after loop

__device__ __nv_bfloat16 g_khi[16 * 2048 * 64];
__device__ __nv_bfloat16 g_klo[16 * 2048 * 64];
__device__ __nv_bfloat16 g_vhi[16 * 2048 * 64];
__device__ __nv_bfloat16 g_vlo[16 * 2048 * 64];
__device__ int g_posm[2 * 2048];

__device__ __forceinline__ uint32_t smem_u32(const void* p) {
    uint32_t a;
    asm("{ .reg .u64 t; cvta.to.shared.u64 t, %1; cvt.u32.u64 %0, t; }" : "=r"(a) : "l"(p));
    return a;
}
__device__ __forceinline__ void ldsm4(uint32_t a, uint32_t r[4]) {
    asm volatile("ldmatrix.sync.aligned.m8n8.x4.shared.b16 {%0,%1,%2,%3}, [%4];"
        : "=r"(r[0]), "=r"(r[1]), "=r"(r[2]), "=r"(r[3]) : "r"(a));
}
__device__ __forceinline__ void ldsm2(uint32_t a, uint32_t r[2]) {
    asm volatile("ldmatrix.sync.aligned.m8n8.x2.shared.b16 {%0,%1}, [%2];"
        : "=r"(r[0]), "=r"(r[1]) : "r"(a));
}
__device__ __forceinline__ void ldsm2t(uint32_t a, uint32_t r[2]) {
    asm volatile("ldmatrix.sync.aligned.m8n8.x2.trans.shared.b16 {%0,%1}, [%2];"
        : "=r"(r[0]), "=r"(r[1]) : "r"(a));
}
__device__ __forceinline__ void mma16816(float d[4], const uint32_t a[4], const uint32_t b[2]) {
    asm volatile("mma.sync.aligned.m16n8k16.row.col.f32.bf16.bf16.f32 "
        "{%0,%1,%2,%3}, {%4,%5,%6,%7}, {%8,%9}, {%0,%1,%2,%3};"
        : "+f"(d[0]), "+f"(d[1]), "+f"(d[2]), "+f"(d[3])
        : "r"(a[0]), "r"(a[1]), "r"(a[2]), "r"(a[3]), "r"(b[0]), "r"(b[1]));
}
__device__ __forceinline__ void mma16828(float d[4], const uint32_t a[2], uint32_t b) {
    asm volatile("mma.sync.aligned.m16n8k8.row.col.f32.bf16.bf16.f32 "
        "{%0,%1,%2,%3}, {%4,%5}, {%6}, {%0,%1,%2,%3};"
        : "+f"(d[0]), "+f"(d[1]), "+f"(d[2]), "+f"(d[3])
        : "r"(a[0]), "r"(a[1]), "r"(b));
}
__device__ __forceinline__ void cvt_hilo(float4 x, uint32_t& h01, uint32_t& h23,
                                         uint32_t& l01, uint32_t& l23) {
    __nv_bfloat162 a = __floats2bfloat162_rn(x.x, x.y);
    __nv_bfloat162 b = __floats2bfloat162_rn(x.z, x.w);
    float2 fa = __bfloat1622float2(a), fb = __bfloat1622float2(b);
    __nv_bfloat162 la = __floats2bfloat162_rn(x.x - fa.x, x.y - fa.y);
    __nv_bfloat162 lb = __floats2bfloat162_rn(x.z - fb.x, x.w - fb.y);
    h01 = *reinterpret_cast<uint32_t*>(&a);  h23 = *reinterpret_cast<uint32_t*>(&b);
    l01 = *reinterpret_cast<uint32_t*>(&la); l23 = *reinterpret_cast<uint32_t*>(&lb);
}
__device__ __forceinline__ uint32_t pack_hi(float a, float b, uint32_t& lo) {
    __nv_bfloat162 h = __floats2bfloat162_rn(a, b);
    float2 hf = __bfloat1622float2(h);
    __nv_bfloat162 l = __floats2bfloat162_rn(a - hf.x, b - hf.y);
    lo = *reinterpret_cast<uint32_t*>(&l);
    return *reinterpret_cast<uint32_t*>(&h);
}
__device__ __forceinline__ float fexp(float x) {
    const float L2E = 1.4426950408889634f;
    float y = fmaf(x, L2E, 12582912.0f);
    int   im = __float_as_int(y) << 23;
    float i  = y - 12582912.0f;
    float f  = fmaf(x, L2E, -i);
    float p  =        1.3333558146e-3f;
    p = fmaf(p, f,    9.6181291076e-3f);
    p = fmaf(p, f,    5.5504108664e-2f);
    p = fmaf(p, f,    2.4022650696e-1f);
    p = fmaf(p, f,    6.9314718056e-1f);
    p = fmaf(p, f,    1.0f);
    return p * __int_as_float(im + 0x3f800000);
}
#define CP_ASYNC16(sm, gp) \
    asm volatile("cp.async.cg.shared.global [%0], [%1], 16;" :: "r"(sm), "l"(gp) : "memory")
#define CP_COMMIT() asm volatile("cp.async.commit_group;" ::: "memory")
#define CP_WAIT1()  asm volatile("cp.async.wait_group 1;" ::: "memory")
#define CP_WAIT0()  asm volatile("cp.async.wait_group 0;" ::: "memory")

// copy THIS warp's 8-row slice (4 regions) of chunk starting at s-row n0
__device__ __forceinline__ void issue_slice_w(uint32_t sb, int n0, int wslice, int lane,
    const __nv_bfloat16* khp, const __nv_bfloat16* klp,
    const __nv_bfloat16* vhp, const __nv_bfloat16* vlp)
{
    #pragma unroll
    for (int j = 0; j < 8; j++) {
        const int i = lane + j * 32;          // 256 = 4 regions * 8 rows * 8 c16
        const int region = i >> 6, w = i & 63;
        const int s = w >> 3, c16 = w & 7;
        const int row = wslice * 8 + s;
        const __nv_bfloat16* gp =
            (region == 0 ? khp : region == 1 ? klp : region == 2 ? vhp : vlp)
            + (size_t)(n0 + row) * 64 + c16 * 8;
        CP_ASYNC16(sb + region * 18432 + row * 144 + c16 * 16, gp);
    }
}

// ============== prep: fp32 -> bf16 hi/lo for K and V, plus posm ==============
__global__ __launch_bounds__(256)
void prep_kv(const float* __restrict__ K, const float* __restrict__ V,
             const int* __restrict__ mk, const int* __restrict__ pos,
             const int* __restrict__ cm)
{
    const int gid = blockIdx.x * 256 + threadIdx.x;     // 1048576
    const int isv = gid >> 19;
    const int g   = gid & 524287;
    const int row = g >> 4, v = g & 15;                 // row over (b,s,h)
    const int b = row >> 14, s = (row >> 3) & 2047, h = row & 7;
    const float* src = isv ? V : K;
    const float4 x = *reinterpret_cast<const float4*>(src + (size_t)row * 64 + 4 * v);
    uint32_t h01, h23, l01, l23; cvt_hilo(x, h01, h23, l01, l23);
    const size_t o = ((size_t)(b * 8 + h) * 2048 + s) * 64 + 4 * v;
    uint32_t* hp = reinterpret_cast<uint32_t*>((isv ? g_vhi : g_khi) + o);
    uint32_t* lp = reinterpret_cast<uint32_t*>((isv ? g_vlo : g_klo) + o);
    hp[0] = h01; hp[1] = h23; lp[0] = l01; lp[1] = l23;
    if (gid < 2 * 2048)
        g_posm[gid] = mk[gid] ? 0x7FFFFFFF : (cm[0] ? pos[gid] : (int)0x80000000);
}

// ============== main kernel: fully warp-autonomous ==============
__global__ __launch_bounds__(NTHR, 1)
void attn_kernel(const float* __restrict__ Q,
                 const int* __restrict__ mq, const int* __restrict__ pos,
                 const int* __restrict__ cmaskp,
                 float* __restrict__ outV, float* __restrict__ outA,
                 float* __restrict__ outE)
{
    extern __shared__ char smc[];
    const uint32_t smb = smem_u32(smc);
    const int t = threadIdx.x, warp = t >> 5, lane = t & 31;
    const int causal = cmaskp[0];

    const int idx = blockIdx.x;          // 2048
    const int lt  = 127 - (idx >> 4);    // heavy tiles first
    const int bh  = idx & 15;
    const int b = bh >> 3, h = bh & 7;
    const int l0 = lt * TL;
    const int nch = causal ? ((lt >> 3) + 1) : (Sq / TS);
    const int ncs = nch * TS;

    float* sSum = (float*)(smc + OFF_SUM);
    float* sDot = (float*)(smc + OFF_DOT);
    float* sInv = (float*)(smc + OFF_INV);

    const __nv_bfloat16* khp = g_khi + ((size_t)bh << 17);
    const __nv_bfloat16* klp = g_klo + ((size_t)bh << 17);
    const __nv_bfloat16* vhp = g_vhi + ((size_t)bh << 17);
    const __nv_bfloat16* vlp = g_vlo + ((size_t)bh << 17);

    // ---- Q tile (16 rows) -> smem hi/lo (stage-2 space) ----
    if (t < 256) {
        const int r = t >> 4, v = t & 15;
        const float4 x = *reinterpret_cast<const float4*>(
            Q + (((size_t)b * Lq + l0 + r) * Hq + h) * Eq + 4 * v);
        uint32_t h01, h23, l01, l23; cvt_hilo(x, h01, h23, l01, l23);
        uint32_t* hp = (uint32_t*)(smc + OFF_QHI + r * 144 + v * 8);
        uint32_t* lp = (uint32_t*)(smc + OFF_QLO + r * 144 + v * 8);
        hp[0] = h01; hp[1] = h23; lp[0] = l01; lp[1] = l23;
    }
    __syncthreads();     // Q smem visible to all warps

    // ---- persistent Q fragments (all warps, same 16 rows) ----
    uint32_t aq[2][4][4];
    {
        const int row = lane & 15, coff = (lane >> 4) * 8;
        #pragma unroll
        for (int kk = 0; kk < 4; kk++) {
            ldsm4(smb + OFF_QHI + row * 144 + (kk * 16 + coff) * 2, aq[0][kk]);
            ldsm4(smb + OFF_QLO + row * 144 + (kk * 16 + coff) * 2, aq[1][kk]);
        }
    }
    __syncthreads();     // all Q frags in regs before any warp refills stage 2

    // ---- each warp issues ITS slice of chunks 0 and 1 ----
    issue_slice_w(smb + 0 * STG_SZ, 0, warp, lane, khp, klp, vhp, vlp);
    CP_COMMIT();
    if (nch > 1) issue_slice_w(smb + 1 * STG_SZ, TS, warp, lane, khp, klp, vhp, vlp);
    CP_COMMIT();

    const int pl_lo = pos[b * Lq + l0 + (lane >> 2)];
    const int pl_hi = pos[b * Lq + l0 + 8 + (lane >> 2)];
    const int* pmrow = g_posm + b * 2048;

    float* aRowLo = outA + ((size_t)bh * Lq + l0 + (lane >> 2)) * Sq;
    float* aRowHi = aRowLo + (size_t)8 * Sq;

    float o[8][4];
    #pragma unroll
    for (int nt = 0; nt < 8; nt++)
        #pragma unroll
        for (int j = 0; j < 4; j++) o[nt][j] = 0.f;
    float rs[2] = {0.f, 0.f}, rd[2] = {0.f, 0.f};

    const uint32_t brow = (uint32_t)(warp * 8 + (lane & 7)) * 144;
    const uint32_t vboff = (uint32_t)(warp * 8 + (lane & 7)) * 144
                         + (uint32_t)((lane >> 3) & 1) * 16;   // nt-pair col select

    int stC = 0;   // stage holding chunk ch (per-warp private slice regions)
    for (int ch = 0; ch < nch; ch++) {
        const int c0 = ch * TS;
        CP_WAIT1();          // my slice of chunk ch resident (per-thread groups)
        __syncwarp();        // cross-lane visibility within the warp

        // issue chunk ch+2 into the stage my reads of ch-1 are done with
        {
            const int nc = ch + 2;
            if (nc < nch) {
                int stN = stC + 2; if (stN >= 3) stN -= 3;
                issue_slice_w(smb + stN * STG_SZ, nc * TS, warp, lane, khp, klp, vhp, vlp);
            }
            CP_COMMIT();
        }

        const uint32_t sb = smb + stC * STG_SZ;
        // hoisted mask/pos
        const int2 pm = *reinterpret_cast<const int2*>(pmrow + c0 + warp * 8 + (lane & 3) * 2);

        // ---- QK^T over this warp's 8 s-cols ----
        float d[4] = {0.f, 0.f, 0.f, 0.f};
        #pragma unroll
        for (int kk = 0; kk < 4; kk++) {
            const uint32_t bco = (uint32_t)(kk * 16 + ((lane >> 3) & 1) * 8) * 2;
            uint32_t bh2[2], bl2[2];
            ldsm2(sb + R_KHI + brow + bco, bh2);
            ldsm2(sb + R_KLO + brow + bco, bl2);
            mma16816(d, aq[0][kk], bh2);
            mma16816(d, aq[0][kk], bl2);
            mma16816(d, aq[1][kk], bh2);
        }
        // ---- epilogue: mask/exp/sums, build m16n8k8 A-fragments ----
        uint32_t ahi[2], alo[2];
        {
            const int c = c0 + warp * 8 + (lane & 3) * 2;
            const float v0 = (pm.x > pl_lo) ? -60.f : d[0] * SCALE;
            const float v1 = (pm.y > pl_lo) ? -60.f : d[1] * SCALE;
            const float v2 = (pm.x > pl_hi) ? -60.f : d[2] * SCALE;
            const float v3 = (pm.y > pl_hi) ? -60.f : d[3] * SCALE;
            const float e0 = fexp(v0), e1 = fexp(v1), e2 = fexp(v2), e3 = fexp(v3);
            ahi[0] = pack_hi(e0, e1, alo[0]);
            ahi[1] = pack_hi(e2, e3, alo[1]);
            rs[0] += e0 + e1;           rs[1] += e2 + e3;
            rd[0] += e0 * v0 + e1 * v1; rd[1] += e2 * v2 + e3 * v3;
            *reinterpret_cast<float2*>(aRowLo + c) = make_float2(e0, e1);
            *reinterpret_cast<float2*>(aRowHi + c) = make_float2(e2, e3);
        }
        // ---- AV: O += A(16x8) * V(8x64) via m16n8k8, 4 nt-pairs ----
        #pragma unroll
        for (int np = 0; np < 4; np++) {
            uint32_t bh2[2], bl2[2];
            ldsm2t(sb + R_VHI + vboff + np * 32, bh2);
            ldsm2t(sb + R_VLO + vboff + np * 32, bl2);
            mma16828(o[2 * np],     ahi, bh2[0]);
            mma16828(o[2 * np + 1], ahi, bh2[1]);
            mma16828(o[2 * np],     ahi, bl2[0]);
            mma16828(o[2 * np + 1], ahi, bl2[1]);
            mma16828(o[2 * np],     alo, bh2[0]);
            mma16828(o[2 * np + 1], alo, bh2[1]);
        }
        stC = (stC + 1 == 3) ? 0 : stC + 1;
    }

    // ---- row sum/dot partials ----
    #pragma unroll
    for (int k = 1; k <= 2; k <<= 1) {
        rs[0] += __shfl_xor_sync(0xffffffffu, rs[0], k);
        rs[1] += __shfl_xor_sync(0xffffffffu, rs[1], k);
        rd[0] += __shfl_xor_sync(0xffffffffu, rd[0], k);
        rd[1] += __shfl_xor_sync(0xffffffffu, rd[1], k);
    }
    if ((lane & 3) == 0) {
        const int r = lane >> 2;
        sSum[r * 16 + warp]       = rs[0];
        sSum[(r + 8) * 16 + warp] = rs[1];
        sDot[r * 16 + warp]       = rd[0];
        sDot[(r + 8) * 16 + warp] = rd[1];
    }
    CP_WAIT0();
    __syncthreads();     // all warps done with final chunks before stage-0 reuse

    // ---- O partials -> sRed (aliases stage 0) ----
    float* sRed = (float*)(smc + OFF_RED);   // [16 warps][16 rows][64]
    {
        const int r = lane >> 2, c = (lane & 3) * 2;
        #pragma unroll
        for (int nt = 0; nt < 8; nt++) {
            *reinterpret_cast<float2*>(&sRed[(warp * TL + r) * 64 + nt * 8 + c])     = make_float2(o[nt][0], o[nt][1]);
            *reinterpret_cast<float2*>(&sRed[(warp * TL + r + 8) * 64 + nt * 8 + c]) = make_float2(o[nt][2], o[nt][3]);
        }
    }
    __syncthreads();
    if (t < TL) {
        float S = 0.f, Dd = 0.f;
        #pragma unroll
        for (int w = 0; w < 16; w++) { S += sSum[t * 16 + w]; Dd += sDot[t * 16 + w]; }
        const float zf = mq[b * Lq + l0 + t] ? 0.f : 1.f;
        sInv[t] = zf / S;
        outE[((size_t)b * Hq + h) * Lq + l0 + t] = zf * (__logf(S) - Dd / S);
    }
    __syncthreads();

    // ---- V output (16 rows x 64 cols) ----
    if (t < 256) {
        const int r = t >> 4, c4 = (t & 15) * 4;
        float4 acc = make_float4(0.f, 0.f, 0.f, 0.f);
        #pragma unroll
        for (int w = 0; w < 16; w++) {
            const float4 x = *reinterpret_cast<const float4*>(&sRed[(w * TL + r) * 64 + c4]);
            acc.x += x.x; acc.y += x.y; acc.z += x.z; acc.w += x.w;
        }
        const float inv = sInv[r];
        acc.x *= inv; acc.y *= inv; acc.z *= inv; acc.w *= inv;
        *reinterpret_cast<float4*>(
            &outV[(((size_t)b * Lq + l0 + r) * Hq + h) * Eq + c4]) = acc;
    }

    // ---- normalize A in place (L2-resident) + zero tail ----
    for (int p = t; p < TL * (Sq / 4); p += NTHR) {
        const int r = p >> 9;
        const int c4 = (p & 511) * 4;
        float4* ap = reinterpret_cast<float4*>(
            outA + ((size_t)bh * Lq + l0 + r) * Sq + c4);
        float4 v;
        if (c4 < ncs) {
            v = *ap;
            const float inv = sInv[r];
            v.x *= inv; v.y *= inv; v.z *= inv; v.w *= inv;
        } else {
            v = make_float4(0.f, 0.f, 0.f, 0.f);
        }
        *ap = v;
    }
}

extern "C" void kernel_launch(void* const* d_in, const int* in_sizes, int n_in,
                              void* d_out, int out_size) {
    const float* Q  = (const float*)d_in[0];
    const float* K  = (const float*)d_in[1];
    const float* V  = (const float*)d_in[2];
    const int* mk   = (const int*)d_in[3];
    const int* mq   = (const int*)d_in[4];
    const int* pos  = (const int*)d_in[5];
    const int* cm   = (const int*)d_in[6];
    float* out  = (float*)d_out;
    float* outV = out;
    float* outA = out + (size_t)Bq * Lq * Hq * Eq;
    float* outE = outA + (size_t)Bq * Hq * Lq * Sq;

    prep_kv<<<4096, 256>>>(K, V, mk, pos, cm);
    cudaFuncSetAttribute(attn_kernel,
                         cudaFuncAttributeMaxDynamicSharedMemorySize, SMEM_TOTAL);
    attn_kernel<<<Bq * Hq * (Lq / TL), NTHR, SMEM_TOTAL>>>(Q, mq, pos, cm,
                                                           outV, outA, outE);
}

// round 16
// speedup vs baseline: 2.0438x; 2.0438x over previous
#include <cuda_runtime.h>
#include <cuda_bf16.h>
#include <math.h>
#include <stdint.h>

#define Bq 2
#define Lq 2048
#define Sq 2048
#define Hq 8
#define Eq 64
#define TL 32
#define TS 128
#define NTHR 512
#define SCALE 0.125f

// smem layout (bytes): 3 stages, Q aliased into stage 2, sums after stages
#define STG_SZ   73728              // one stage: KHI|KLO|VHI|VLO, each 128*144
#define R_KHI    0
#define R_KLO    18432
#define R_VHI    36864
#define R_VLO    55296
#define OFF_QHI  147456             // stage-2 space (dead after prologue)
#define OFF_QLO  152064
#define OFF_SUM  221184
#define OFF_DOT  222208
#define OFF_INV  223232
#define SMEM_TOTAL 223360
#define OFF_RED  0                  // 64KB O-partials alias stage 0 after loop

__device__ __nv_bfloat16 g_khi[16 * 2048 * 64];
__device__ __nv_bfloat16 g_klo[16 * 2048 * 64];
__device__ __nv_bfloat16 g_vhi[16 * 2048 * 64];
__device__ __nv_bfloat16 g_vlo[16 * 2048 * 64];
__device__ int g_posm[2 * 2048];

__device__ __forceinline__ uint32_t smem_u32(const void* p) {
    uint32_t a;
    asm("{ .reg .u64 t; cvta.to.shared.u64 t, %1; cvt.u32.u64 %0, t; }" : "=r"(a) : "l"(p));
    return a;
}
__device__ __forceinline__ void ldsm4(uint32_t a, uint32_t r[4]) {
    asm volatile("ldmatrix.sync.aligned.m8n8.x4.shared.b16 {%0,%1,%2,%3}, [%4];"
        : "=r"(r[0]), "=r"(r[1]), "=r"(r[2]), "=r"(r[3]) : "r"(a));
}
__device__ __forceinline__ void ldsm2(uint32_t a, uint32_t r[2]) {
    asm volatile("ldmatrix.sync.aligned.m8n8.x2.shared.b16 {%0,%1}, [%2];"
        : "=r"(r[0]), "=r"(r[1]) : "r"(a));
}
__device__ __forceinline__ void ldsm2t(uint32_t a, uint32_t r[2]) {
    asm volatile("ldmatrix.sync.aligned.m8n8.x2.trans.shared.b16 {%0,%1}, [%2];"
        : "=r"(r[0]), "=r"(r[1]) : "r"(a));
}
__device__ __forceinline__ void mma16816(float d[4], const uint32_t a[4], const uint32_t b[2]) {
    asm volatile("mma.sync.aligned.m16n8k16.row.col.f32.bf16.bf16.f32 "
        "{%0,%1,%2,%3}, {%4,%5,%6,%7}, {%8,%9}, {%0,%1,%2,%3};"
        : "+f"(d[0]), "+f"(d[1]), "+f"(d[2]), "+f"(d[3])
        : "r"(a[0]), "r"(a[1]), "r"(a[2]), "r"(a[3]), "r"(b[0]), "r"(b[1]));
}
__device__ __forceinline__ void cvt_hilo(float4 x, uint32_t& h01, uint32_t& h23,
                                         uint32_t& l01, uint32_t& l23) {
    __nv_bfloat162 a = __floats2bfloat162_rn(x.x, x.y);
    __nv_bfloat162 b = __floats2bfloat162_rn(x.z, x.w);
    float2 fa = __bfloat1622float2(a), fb = __bfloat1622float2(b);
    __nv_bfloat162 la = __floats2bfloat162_rn(x.x - fa.x, x.y - fa.y);
    __nv_bfloat162 lb = __floats2bfloat162_rn(x.z - fb.x, x.w - fb.y);
    h01 = *reinterpret_cast<uint32_t*>(&a);  h23 = *reinterpret_cast<uint32_t*>(&b);
    l01 = *reinterpret_cast<uint32_t*>(&la); l23 = *reinterpret_cast<uint32_t*>(&lb);
}
__device__ __forceinline__ uint32_t pack_hi(float a, float b, uint32_t& lo) {
    __nv_bfloat162 h = __floats2bfloat162_rn(a, b);
    float2 hf = __bfloat1622float2(h);
    __nv_bfloat162 l = __floats2bfloat162_rn(a - hf.x, b - hf.y);
    lo = *reinterpret_cast<uint32_t*>(&l);
    return *reinterpret_cast<uint32_t*>(&h);
}
__device__ __forceinline__ float fexp(float x) {
    const float L2E = 1.4426950408889634f;
    float y = fmaf(x, L2E, 12582912.0f);
    int   im = __float_as_int(y) << 23;
    float i  = y - 12582912.0f;
    float f  = fmaf(x, L2E, -i);
    float p  =        1.3333558146e-3f;
    p = fmaf(p, f,    9.6181291076e-3f);
    p = fmaf(p, f,    5.5504108664e-2f);
    p = fmaf(p, f,    2.4022650696e-1f);
    p = fmaf(p, f,    6.9314718056e-1f);
    p = fmaf(p, f,    1.0f);
    return p * __int_as_float(im + 0x3f800000);
}
#define CP_ASYNC16(sm, gp) \
    asm volatile("cp.async.cg.shared.global [%0], [%1], 16;" :: "r"(sm), "l"(gp) : "memory")
#define CP_COMMIT() asm volatile("cp.async.commit_group;" ::: "memory")
#define CP_WAIT1()  asm volatile("cp.async.wait_group 1;" ::: "memory")
#define CP_WAIT0()  asm volatile("cp.async.wait_group 0;" ::: "memory")
#define BAR_PAIR(id) asm volatile("bar.sync %0, 64;" :: "r"(id) : "memory")

// copy THIS pair's 16-row slice (4 regions) of chunk starting at s-row n0
__device__ __forceinline__ void issue_slice(uint32_t sb, int n0, int ks, int lane,
    const __nv_bfloat16* khp, const __nv_bfloat16* klp,
    const __nv_bfloat16* vhp, const __nv_bfloat16* vlp)
{
    #pragma unroll
    for (int j = 0; j < 16; j++) {
        const int i = lane + j * 32;          // 512 = 4 regions * 16 rows * 8 c16
        const int region = i >> 7, w = i & 127;
        const int s = w >> 3, c16 = w & 7;
        const int row = ks * 16 + s;
        const __nv_bfloat16* gp =
            (region == 0 ? khp : region == 1 ? klp : region == 2 ? vhp : vlp)
            + (size_t)(n0 + row) * 64 + c16 * 8;
        CP_ASYNC16(sb + region * 18432 + row * 144 + c16 * 16, gp);
    }
}

// ============== prep: fp32 -> bf16 hi/lo for K and V, plus posm ==============
__global__ __launch_bounds__(256)
void prep_kv(const float* __restrict__ K, const float* __restrict__ V,
             const int* __restrict__ mk, const int* __restrict__ pos,
             const int* __restrict__ cm)
{
    const int gid = blockIdx.x * 256 + threadIdx.x;     // 1048576
    const int isv = gid >> 19;
    const int g   = gid & 524287;
    const int row = g >> 4, v = g & 15;                 // row over (b,s,h)
    const int b = row >> 14, s = (row >> 3) & 2047, h = row & 7;
    const float* src = isv ? V : K;
    const float4 x = *reinterpret_cast<const float4*>(src + (size_t)row * 64 + 4 * v);
    uint32_t h01, h23, l01, l23; cvt_hilo(x, h01, h23, l01, l23);
    const size_t o = ((size_t)(b * 8 + h) * 2048 + s) * 64 + 4 * v;
    uint32_t* hp = reinterpret_cast<uint32_t*>((isv ? g_vhi : g_khi) + o);
    uint32_t* lp = reinterpret_cast<uint32_t*>((isv ? g_vlo : g_klo) + o);
    hp[0] = h01; hp[1] = h23; lp[0] = l01; lp[1] = l23;
    if (gid < 2 * 2048)
        g_posm[gid] = mk[gid] ? 0x7FFFFFFF : (cm[0] ? pos[gid] : (int)0x80000000);
}

// ============== main kernel ==============
__global__ __launch_bounds__(NTHR, 1)
void attn_kernel(const float* __restrict__ Q,
                 const int* __restrict__ mq, const int* __restrict__ pos,
                 const int* __restrict__ cmaskp,
                 float* __restrict__ outV, float* __restrict__ outA,
                 float* __restrict__ outE)
{
    extern __shared__ char smc[];
    const uint32_t smb = smem_u32(smc);
    const int t = threadIdx.x, warp = t >> 5, lane = t & 31;
    // pair = (w, w^2): partners live on DIFFERENT SMSPs -> 4 independent
    // streams per SMSP instead of 2 (R12 had pair = (w, w+8), same SMSP)
    const int rh = (warp >> 1) & 1;                  // row-half 0/1
    const int ks = ((warp >> 2) << 1) | (warp & 1);  // s/k slice 0..7
    const int causal = cmaskp[0];

    const int idx = blockIdx.x;          // 1024
    const int lt  = 63 - (idx >> 4);
    const int bh  = idx & 15;
    const int b = bh >> 3, h = bh & 7;
    const int l0 = lt * TL;
    const int nch = causal ? ((lt >> 2) + 1) : (Sq / TS);
    const int ncs = nch * TS;

    float* sSum = (float*)(smc + OFF_SUM);
    float* sDot = (float*)(smc + OFF_DOT);
    float* sInv = (float*)(smc + OFF_INV);

    const __nv_bfloat16* khp = g_khi + ((size_t)bh << 17);
    const __nv_bfloat16* klp = g_klo + ((size_t)bh << 17);
    const __nv_bfloat16* vhp = g_vhi + ((size_t)bh << 17);
    const __nv_bfloat16* vlp = g_vlo + ((size_t)bh << 17);

    // ---- Q tile -> smem hi/lo (stage-2 space) ----
    {
        const int r = t >> 4, v = t & 15;
        const float4 x = *reinterpret_cast<const float4*>(
            Q + (((size_t)b * Lq + l0 + r) * Hq + h) * Eq + 4 * v);
        uint32_t h01, h23, l01, l23; cvt_hilo(x, h01, h23, l01, l23);
        uint32_t* hp = (uint32_t*)(smc + OFF_QHI + r * 144 + v * 8);
        uint32_t* lp = (uint32_t*)(smc + OFF_QLO + r * 144 + v * 8);
        hp[0] = h01; hp[1] = h23; lp[0] = l01; lp[1] = l23;
    }
    // ---- producers issue their slices of chunks 0 and 1 (stages 0,1) ----
    if (rh == 0) {
        issue_slice(smb + 0 * STG_SZ, 0, ks, lane, khp, klp, vhp, vlp);
        CP_COMMIT();
        if (nch > 1) issue_slice(smb + 1 * STG_SZ, TS, ks, lane, khp, klp, vhp, vlp);
        CP_COMMIT();
    }
    __syncthreads();     // Q smem visible to all warps

    // ---- persistent Q fragments ----
    uint32_t aq[2][4][4];
    {
        const int row = rh * 16 + (lane & 15), coff = (lane >> 4) * 8;
        #pragma unroll
        for (int kk = 0; kk < 4; kk++) {
            ldsm4(smb + OFF_QHI + row * 144 + (kk * 16 + coff) * 2, aq[0][kk]);
            ldsm4(smb + OFF_QLO + row * 144 + (kk * 16 + coff) * 2, aq[1][kk]);
        }
    }
    __syncthreads();     // all Q frags loaded before any pair refills stage 2

    const int pl_lo = pos[b * Lq + l0 + rh * 16 + (lane >> 2)];
    const int pl_hi = pos[b * Lq + l0 + rh * 16 + 8 + (lane >> 2)];
    const int* pmrow = g_posm + b * 2048;

    float* aRowLo = outA + ((size_t)bh * Lq + l0 + rh * 16 + (lane >> 2)) * Sq;
    float* aRowHi = aRowLo + (size_t)8 * Sq;

    float o[8][4];
    #pragma unroll
    for (int nt = 0; nt < 8; nt++)
        #pragma unroll
        for (int j = 0; j < 4; j++) o[nt][j] = 0.f;
    float rs[2] = {0.f, 0.f}, rd[2] = {0.f, 0.f};

    int stC = 0;   // stage holding chunk ch
    for (int ch = 0; ch < nch; ch++) {
        const int c0 = ch * TS;
        if (rh == 0) CP_WAIT1();      // producer: my slice of chunk ch resident
        BAR_PAIR(ks + 1);             // pair sync: data visible, prior stage reads done
        if (rh == 0) {
            const int nc = ch + 2;
            if (nc < nch) {
                int stN = stC + 2; if (stN >= 3) stN -= 3;
                issue_slice(smb + stN * STG_SZ, nc * TS, ks, lane, khp, klp, vhp, vlp);
            }
            CP_COMMIT();
        }

        const uint32_t sb = smb + stC * STG_SZ;
        // hoisted mask/pos loads (latency overlapped with MMAs below)
        const int2 pm0 = *reinterpret_cast<const int2*>(pmrow + c0 + ks * 16 + (lane & 3) * 2);
        const int2 pm1 = *reinterpret_cast<const int2*>(pmrow + c0 + ks * 16 + 8 + (lane & 3) * 2);

        uint32_t ahi[4], alo[4];
        // ---- QK^T ----
        {
            float d0[4] = {0.f, 0.f, 0.f, 0.f}, d1[4] = {0.f, 0.f, 0.f, 0.f};
            const uint32_t brow0 = (uint32_t)(ks * 16 + (lane & 7)) * 144;
            #pragma unroll
            for (int kk = 0; kk < 4; kk++) {
                const uint32_t bco = (uint32_t)(kk * 16 + ((lane >> 3) & 1) * 8) * 2;
                uint32_t b0h[2], b0l[2], b1h[2], b1l[2];
                ldsm2(sb + R_KHI + brow0 + bco, b0h);
                ldsm2(sb + R_KLO + brow0 + bco, b0l);
                ldsm2(sb + R_KHI + brow0 + 8 * 144 + bco, b1h);
                ldsm2(sb + R_KLO + brow0 + 8 * 144 + bco, b1l);
                mma16816(d0, aq[0][kk], b0h);
                mma16816(d1, aq[0][kk], b1h);
                mma16816(d0, aq[0][kk], b0l);
                mma16816(d1, aq[0][kk], b1l);
                mma16816(d0, aq[1][kk], b0h);
                mma16816(d1, aq[1][kk], b1h);
            }
            #pragma unroll
            for (int nt = 0; nt < 2; nt++) {
                float* d = nt ? d1 : d0;
                const int2 pm = nt ? pm1 : pm0;
                const int c = c0 + ks * 16 + nt * 8 + (lane & 3) * 2;
                const float v0 = (pm.x > pl_lo) ? -60.f : d[0] * SCALE;
                const float v1 = (pm.y > pl_lo) ? -60.f : d[1] * SCALE;
                const float v2 = (pm.x > pl_hi) ? -60.f : d[2] * SCALE;
                const float v3 = (pm.y > pl_hi) ? -60.f : d[3] * SCALE;
                const float e0 = fexp(v0), e1 = fexp(v1), e2 = fexp(v2), e3 = fexp(v3);
                ahi[nt * 2 + 0] = pack_hi(e0, e1, alo[nt * 2 + 0]);
                ahi[nt * 2 + 1] = pack_hi(e2, e3, alo[nt * 2 + 1]);
                rs[0] += e0 + e1;           rs[1] += e2 + e3;
                rd[0] += e0 * v0 + e1 * v1; rd[1] += e2 * v2 + e3 * v3;
                *reinterpret_cast<float2*>(aRowLo + c) = make_float2(e0, e1);
                *reinterpret_cast<float2*>(aRowHi + c) = make_float2(e2, e3);
            }
        }
        // ---- AV ----
        {
            const uint32_t vrow = (uint32_t)(ks * 16 + (lane & 7) + ((lane >> 3) & 1) * 8) * 144;
            #pragma unroll
            for (int nt = 0; nt < 8; nt++) {
                uint32_t bh2[2], bl2[2];
                ldsm2t(sb + R_VHI + vrow + nt * 16, bh2);
                ldsm2t(sb + R_VLO + vrow + nt * 16, bl2);
                mma16816(o[nt], ahi, bh2);
                mma16816(o[nt], ahi, bl2);
                mma16816(o[nt], alo, bh2);
            }
        }
        stC = (stC + 1 == 3) ? 0 : stC + 1;
    }

    // ---- row sum/dot partials (non-aliasing region; safe pre-sync) ----
    #pragma unroll
    for (int k = 1; k <= 2; k <<= 1) {
        rs[0] += __shfl_xor_sync(0xffffffffu, rs[0], k);
        rs[1] += __shfl_xor_sync(0xffffffffu, rs[1], k);
        rd[0] += __shfl_xor_sync(0xffffffffu, rd[0], k);
        rd[1] += __shfl_xor_sync(0xffffffffu, rd[1], k);
    }
    if ((lane & 3) == 0) {
        const int r = rh * 16 + (lane >> 2);
        sSum[r * 8 + ks]       = rs[0];
        sSum[(r + 8) * 8 + ks] = rs[1];
        sDot[r * 8 + ks]       = rd[0];
        sDot[(r + 8) * 8 + ks] = rd[1];
    }
    CP_WAIT0();
    __syncthreads();     // all pairs done with final chunks before stage-0 reuse

    // ---- O partials -> sRed (aliases stage 0) ----
    float* sRed = (float*)(smc + OFF_RED);   // [8 ks][32 rows][64]
    {
        const int r = rh * 16 + (lane >> 2), c = (lane & 3) * 2;
        #pragma unroll
        for (int nt = 0; nt < 8; nt++) {
            *reinterpret_cast<float2*>(&sRed[((ks * TL) + r) * 64 + nt * 8 + c])     = make_float2(o[nt][0], o[nt][1]);
            *reinterpret_cast<float2*>(&sRed[((ks * TL) + r + 8) * 64 + nt * 8 + c]) = make_float2(o[nt][2], o[nt][3]);
        }
    }
    __syncthreads();
    if (t < TL) {
        float S = 0.f, Dd = 0.f;
        #pragma unroll
        for (int w = 0; w < 8; w++) { S += sSum[t * 8 + w]; Dd += sDot[t * 8 + w]; }
        const float zf = mq[b * Lq + l0 + t] ? 0.f : 1.f;
        sInv[t] = zf / S;
        outE[((size_t)b * Hq + h) * Lq + l0 + t] = zf * (__logf(S) - Dd / S);
    }
    __syncthreads();

    // ---- V output ----
    {
        const int r = t >> 4, c4 = (t & 15) * 4;
        float4 acc = make_float4(0.f, 0.f, 0.f, 0.f);
        #pragma unroll
        for (int w = 0; w < 8; w++) {
            const float4 x = *reinterpret_cast<const float4*>(&sRed[(w * TL + r) * 64 + c4]);
            acc.x += x.x; acc.y += x.y; acc.z += x.z; acc.w += x.w;
        }
        const float inv = sInv[r];
        acc.x *= inv; acc.y *= inv; acc.z *= inv; acc.w *= inv;
        *reinterpret_cast<float4*>(
            &outV[(((size_t)b * Lq + l0 + r) * Hq + h) * Eq + c4]) = acc;
    }

    // ---- normalize A in place (L2-resident) + zero tail ----
    for (int p = t; p < TL * (Sq / 4); p += NTHR) {
        const int r = p >> 9;
        const int c4 = (p & 511) * 4;
        float4* ap = reinterpret_cast<float4*>(
            outA + ((size_t)bh * Lq + l0 + r) * Sq + c4);
        float4 v;
        if (c4 < ncs) {
            v = *ap;
            const float inv = sInv[r];
            v.x *= inv; v.y *= inv; v.z *= inv; v.w *= inv;
        } else {
            v = make_float4(0.f, 0.f, 0.f, 0.f);
        }
        *ap = v;
    }
}

extern "C" void kernel_launch(void* const* d_in, const int* in_sizes, int n_in,
                              void* d_out, int out_size) {
    const float* Q  = (const float*)d_in[0];
    const float* K  = (const float*)d_in[1];
    const float* V  = (const float*)d_in[2];
    const int* mk   = (const int*)d_in[3];
    const int* mq   = (const int*)d_in[4];
    const int* pos  = (const int*)d_in[5];
    const int* cm   = (const int*)d_in[6];
    float* out  = (float*)d_out;
    float* outV = out;
    float* outA = out + (size_t)Bq * Lq * Hq * Eq;
    float* outE = outA + (size_t)Bq * Hq * Lq * Sq;

    prep_kv<<<4096, 256>>>(K, V, mk, pos, cm);
    cudaFuncSetAttribute(attn_kernel,
                         cudaFuncAttributeMaxDynamicSharedMemorySize, SMEM_TOTAL);
    attn_kernel<<<Bq * Hq * (Lq / TL), NTHR, SMEM_TOTAL>>>(Q, mq, pos, cm,
                                                           outV, outA, outE);
}